// round 8
// baseline (speedup 1.0000x reference)
#include <cuda_runtime.h>
#include <cuda_fp16.h>
#include <math.h>

#define NN   50000
#define EE   800000
#define IN_DIM 128
#define O1   64
#define O2   128

#define SCAN_B 1024
#define NBLK   ((NN + SCAN_B - 1) / SCAN_B)   // 49

#define PREP_BLOCKS ((EE + 255) / 256)        // 3125
#define G1_BLOCKS   ((NN + 63) / 64)          // 782
#define AGG_BLOCKS  ((NN * 32 + 255) / 256)   // 6250
#define RST_BLOCKS  98                        // zero g_dc (2 ULL/thread) + g_lk

#define DEG_SCALE 1048576.0f                  // 2^20 fixed point for edge-weight sums

// Scratch (device globals — no allocation allowed). Index 0/1 = tower.
__device__ unsigned long long g_dc[2][NN];    // hi32 = count, lo32 = fixedpoint sum(relu(w))
__device__ unsigned long long g_lk[2][64];    // lookback: hi32 flag (0/1/2), lo32 value
__device__ float  g_dinv[2][NN];
__device__ int    g_off [2][NN + 1];          // exclusive offsets (immutable after scan)
__device__ int    g_rank[2][EE];              // per-edge rank within its dst bucket
__device__ int2   g_edge[2][EE];              // (src, float-bits of norm)
__device__ __half g_h1h[2][NN * O1];          // layer-1 hidden fp16 (gather-bound)
__device__ float  g_z1 [2][NN * O1];
__device__ __half g_h2h[2][NN * O2];          // layer-2 hidden fp16 (gather-bound)

// ---------------------------------------------------------------------------
// packed fp32x2 FMA (sm_103a FFMA2)
// ---------------------------------------------------------------------------
__device__ __forceinline__ void ffma2(float2& acc, float2 a, float2 w) {
    unsigned long long ac, av, wv;
    ac = *(unsigned long long*)&acc;
    av = *(unsigned long long*)&a;
    wv = *(unsigned long long*)&w;
    asm("fma.rn.f32x2 %0, %1, %2, %0;" : "+l"(ac) : "l"(av), "l"(wv));
    acc = *(float2*)&ac;
}

// ---------------------------------------------------------------------------
// Register-tiled GEMM body: C[64-row tile, 64-col tile] = A[N,K] @ W[K,OC]
// 256 flat threads; each thread 4 rows x 4 cols; k paired for fma.rn.f32x2
// Output fp16
// ---------------------------------------------------------------------------
template<int K, int OC>
__device__ __forceinline__ void gemm_body(const float* __restrict__ A,
                                          const float* __restrict__ W,
                                          __half* __restrict__ C,
                                          int rowBlk, int colBase, int tid) {
    __shared__ float2 Wp[(K / 2) * 64];
    int tx = tid & 15;
    int ty = tid >> 4;
    for (int idx = tid; idx < (K / 2) * 64; idx += 256) {
        int kp = idx >> 6, c = idx & 63;
        Wp[idx] = make_float2(W[(2 * kp)     * OC + colBase + c],
                              W[(2 * kp + 1) * OC + colBase + c]);
    }
    __syncthreads();

    int r0 = rowBlk * 64 + ty * 4;
    int c0 = tx * 4;
    float2 acc[4][4];
#pragma unroll
    for (int i = 0; i < 4; i++)
#pragma unroll
        for (int j = 0; j < 4; j++) acc[i][j] = make_float2(0.0f, 0.0f);

#pragma unroll 4
    for (int kk = 0; kk < K; kk += 4) {
        float4 a[4];
#pragma unroll
        for (int i = 0; i < 4; i++) {
            int r = r0 + i;
            a[i] = (r < NN) ? *(const float4*)(A + (size_t)r * K + kk)
                            : make_float4(0.0f, 0.0f, 0.0f, 0.0f);
        }
#pragma unroll
        for (int kp = 0; kp < 2; kp++) {
            const float2* wrow = Wp + ((kk >> 1) + kp) * 64 + c0;
            float4 wA = *(const float4*)(wrow);
            float4 wB = *(const float4*)(wrow + 2);
            float2 w0 = make_float2(wA.x, wA.y);
            float2 w1 = make_float2(wA.z, wA.w);
            float2 w2 = make_float2(wB.x, wB.y);
            float2 w3 = make_float2(wB.z, wB.w);
#pragma unroll
            for (int i = 0; i < 4; i++) {
                float2 ap = kp ? make_float2(a[i].z, a[i].w)
                               : make_float2(a[i].x, a[i].y);
                ffma2(acc[i][0], ap, w0);
                ffma2(acc[i][1], ap, w1);
                ffma2(acc[i][2], ap, w2);
                ffma2(acc[i][3], ap, w3);
            }
        }
    }
#pragma unroll
    for (int i = 0; i < 4; i++) {
        int r = r0 + i;
        if (r < NN) {
            __half2 p0 = __floats2half2_rn(acc[i][0].x + acc[i][0].y,
                                           acc[i][1].x + acc[i][1].y);
            __half2 p1 = __floats2half2_rn(acc[i][2].x + acc[i][2].y,
                                           acc[i][3].x + acc[i][3].y);
            uint2 pk;
            pk.x = *(unsigned*)&p0;
            pk.y = *(unsigned*)&p1;
            *(uint2*)(C + (size_t)r * OC + colBase + c0) = pk;
        }
    }
}

// ---------------------------------------------------------------------------
// fused: packed deg/count atomics + rank capture | GEMM1
// (g_dc and g_lk are zero at entry: BSS-zero on first run, reset by the
//  previous invocation's k_aggr2 tail blocks on every subsequent run)
// ---------------------------------------------------------------------------
__global__ void k_prep_gemm1(const int* __restrict__ ei1, const float* __restrict__ ew1,
                             const int* __restrict__ ei2, const float* __restrict__ ew2,
                             const float* __restrict__ x1, const float* __restrict__ x2,
                             const float* __restrict__ W1) {
    int tw = blockIdx.y;
    if (blockIdx.x < PREP_BLOCKS) {
        const int*   ei = tw ? ei2 : ei1;
        const float* ew = tw ? ew2 : ew1;
        int e = blockIdx.x * 256 + threadIdx.x;
        if (e < EE) {
            int d = ei[EE + e];
            float w = fmaxf(ew[e], 0.0f);          // relu(edge_weight)
            unsigned long long pk =
                (1ULL << 32) | (unsigned long long)__float2uint_rn(w * DEG_SCALE);
            unsigned long long old = atomicAdd(&g_dc[tw][d], pk);
            g_rank[tw][e] = (int)(old >> 32);      // rank within dst bucket
        }
    } else {
        gemm_body<IN_DIM, O1>(tw ? x2 : x1, W1, g_h1h[tw],
                              blockIdx.x - PREP_BLOCKS, 0, threadIdx.x);
    }
}

// ---------------------------------------------------------------------------
// single-pass scan (decoupled lookback) + dinv. grid (NBLK,2) x 1024 threads
// ---------------------------------------------------------------------------
__global__ void k_scan() {
    int tw   = blockIdx.y;
    int b    = blockIdx.x;
    int i    = b * SCAN_B + threadIdx.x;
    int lane = threadIdx.x & 31;
    int wid  = threadIdx.x >> 5;
    unsigned long long dc = (i < NN) ? g_dc[tw][i] : 0ULL;
    int c = (int)(dc >> 32);
    int v = c;
#pragma unroll
    for (int d = 1; d < 32; d <<= 1) {
        int t = __shfl_up_sync(0xffffffffu, v, d);
        if (lane >= d) v += t;
    }
    __shared__ int wsum[32];
    if (lane == 31) wsum[wid] = v;
    __syncthreads();
    if (wid == 0) {
        int w = wsum[lane];
#pragma unroll
        for (int d = 1; d < 32; d <<= 1) {
            int t = __shfl_up_sync(0xffffffffu, w, d);
            if (lane >= d) w += t;
        }
        wsum[lane] = w;
    }
    __syncthreads();
    int add = (wid > 0) ? wsum[wid - 1] : 0;
    int incl = v + add;                   // inclusive within block
    int total = wsum[31];

    __shared__ int s_exc;
    if (threadIdx.x == 0) {
        unsigned long long flag = (b == 0) ? 2ULL : 1ULL;
        atomicExch(&g_lk[tw][b], (flag << 32) | (unsigned)total);
        int exc = 0;
        if (b > 0) {
            int p = b - 1;
            while (true) {
                unsigned long long pv = *((volatile unsigned long long*)&g_lk[tw][p]);
                unsigned f = (unsigned)(pv >> 32);
                if (f == 2u) { exc += (int)(unsigned)pv; break; }
                if (f == 1u) { exc += (int)(unsigned)pv; p--; }
            }
            atomicExch(&g_lk[tw][b], (2ULL << 32) | (unsigned)(total + exc));
        }
        s_exc = exc;
    }
    __syncthreads();
    if (i < NN) {
        g_off[tw][i] = s_exc + incl - c;   // exclusive global offset
        float deg = 2.0f + (float)(unsigned)dc * (1.0f / DEG_SCALE);
        g_dinv[tw][i] = rsqrtf(deg);
    }
    if (b == gridDim.x - 1 && threadIdx.x == 0) g_off[tw][NN] = EE;
}

// ---------------------------------------------------------------------------
// fill: atomic-free — pos = off[d] + rank[e]
// ---------------------------------------------------------------------------
__global__ void k_fill(const int* __restrict__ ei1, const float* __restrict__ ew1,
                       const int* __restrict__ ei2, const float* __restrict__ ew2) {
    int tw = blockIdx.y;
    const int*   ei = tw ? ei2 : ei1;
    const float* ew = tw ? ew2 : ew1;
    int e = blockIdx.x * blockDim.x + threadIdx.x;
    if (e < EE) {
        int s = ei[e], d = ei[EE + e];
        float w = fmaxf(ew[e], 0.0f);
        float nrm = g_dinv[tw][s] * w * g_dinv[tw][d];
        int pos = g_off[tw][d] + g_rank[tw][e];
        g_edge[tw][pos] = make_int2(s, __float_as_int(nrm));
    }
}

__global__ void k_gemm2(const float* __restrict__ W2) {
    int tw = blockIdx.z;
    gemm_body<O1, O2>(g_z1[tw], W2, g_h2h[tw],
                      blockIdx.x, blockIdx.y * 64, threadIdx.y * 16 + threadIdx.x);
}

// ---------------------------------------------------------------------------
// Aggregation 1: warp per node, fp16 gather-max over CSR edges (8x unrolled)
// ---------------------------------------------------------------------------
__device__ __forceinline__ void max2_half(float& m0, float& m1, unsigned pk, float w) {
    float2 f = __half22float2(*(__half2*)&pk);
    m0 = fmaxf(m0, w * f.x);
    m1 = fmaxf(m1, w * f.y);
}

__global__ void k_aggr1(const float* __restrict__ b1) {
    int tw   = blockIdx.y;
    int warp = (blockIdx.x * blockDim.x + threadIdx.x) >> 5;
    int lane = threadIdx.x & 31;
    if (warp >= NN) return;
    const int2*   eg = g_edge[tw];
    const __half* h  = g_h1h[tw];
    int beg = g_off[tw][warp];
    int end = g_off[tw][warp + 1];
    float dv = g_dinv[tw][warp];
    float sl = 2.0f * dv * dv;
    unsigned selfpk = *(const unsigned*)(h + (size_t)warp * O1 + lane * 2);
    float m0 = -1e30f, m1 = -1e30f;
    max2_half(m0, m1, selfpk, sl);
    int j = beg;
    for (; j + 8 <= end; j += 8) {
        int2 e[8];
        unsigned v[8];
#pragma unroll
        for (int q = 0; q < 8; q++) e[q] = eg[j + q];
#pragma unroll
        for (int q = 0; q < 8; q++)
            v[q] = *(const unsigned*)(h + (size_t)e[q].x * O1 + lane * 2);
#pragma unroll
        for (int q = 0; q < 8; q++)
            max2_half(m0, m1, v[q], __int_as_float(e[q].y));
    }
    for (; j < end; j++) {
        int2 e = eg[j];
        unsigned v = *(const unsigned*)(h + (size_t)e.x * O1 + lane * 2);
        max2_half(m0, m1, v, __int_as_float(e.y));
    }
    if (!isfinite(m0)) m0 = 0.0f;
    if (!isfinite(m1)) m1 = 0.0f;
    float2 bv = *(const float2*)(b1 + lane * 2);
    *(float2*)(g_z1[tw] + (size_t)warp * O1 + lane * 2) = make_float2(m0 + bv.x, m1 + bv.y);
}

// ---------------------------------------------------------------------------
// Aggregation 2: warp per node over 128 fp16 feats (8B/lane), 8x unrolled;
// tail blocks reset g_dc / g_lk for the next invocation
// ---------------------------------------------------------------------------
__device__ __forceinline__ void max4_half(float& m0, float& m1, float& m2, float& m3,
                                          uint2 pk, float w) {
    float2 f0 = __half22float2(*(__half2*)&pk.x);
    float2 f1 = __half22float2(*(__half2*)&pk.y);
    m0 = fmaxf(m0, w * f0.x); m1 = fmaxf(m1, w * f0.y);
    m2 = fmaxf(m2, w * f1.x); m3 = fmaxf(m3, w * f1.y);
}

__global__ void k_aggr2(const float* __restrict__ b2, float* __restrict__ out) {
    int tw   = blockIdx.y;
    if (blockIdx.x >= AGG_BLOCKS) {
        // reset scratch for next invocation
        int rb  = blockIdx.x - AGG_BLOCKS;
        int idx = (rb * 256 + threadIdx.x) * 2;
        if (idx     < NN) g_dc[tw][idx]     = 0ULL;
        if (idx + 1 < NN) g_dc[tw][idx + 1] = 0ULL;
        if (rb == 0 && threadIdx.x < 64) g_lk[tw][threadIdx.x] = 0ULL;
        return;
    }
    int warp = (blockIdx.x * blockDim.x + threadIdx.x) >> 5;
    int lane = threadIdx.x & 31;
    if (warp >= NN) return;
    const int2*   eg = g_edge[tw];
    const __half* h  = g_h2h[tw];
    float* op = out + (size_t)tw * NN * O2;
    int beg = g_off[tw][warp];
    int end = g_off[tw][warp + 1];
    float dv = g_dinv[tw][warp];
    float sl = 2.0f * dv * dv;
    uint2 selfpk = *(const uint2*)(h + (size_t)warp * O2 + lane * 4);
    float m0 = -1e30f, m1 = -1e30f, m2 = -1e30f, m3 = -1e30f;
    max4_half(m0, m1, m2, m3, selfpk, sl);
    int j = beg;
    for (; j + 8 <= end; j += 8) {
        int2 e[8];
        uint2 v[8];
#pragma unroll
        for (int q = 0; q < 8; q++) e[q] = eg[j + q];
#pragma unroll
        for (int q = 0; q < 8; q++)
            v[q] = *(const uint2*)(h + (size_t)e[q].x * O2 + lane * 4);
#pragma unroll
        for (int q = 0; q < 8; q++)
            max4_half(m0, m1, m2, m3, v[q], __int_as_float(e[q].y));
    }
    for (; j < end; j++) {
        int2 e = eg[j];
        uint2 v = *(const uint2*)(h + (size_t)e.x * O2 + lane * 4);
        max4_half(m0, m1, m2, m3, v, __int_as_float(e.y));
    }
    if (!isfinite(m0)) m0 = 0.0f;
    if (!isfinite(m1)) m1 = 0.0f;
    if (!isfinite(m2)) m2 = 0.0f;
    if (!isfinite(m3)) m3 = 0.0f;
    float4 bv = *(const float4*)(b2 + lane * 4);
    *(float4*)(op + (size_t)warp * O2 + lane * 4) =
        make_float4(m0 + bv.x, m1 + bv.y, m2 + bv.z, m3 + bv.w);
}

// ---------------------------------------------------------------------------
// launch
// ---------------------------------------------------------------------------
extern "C" void kernel_launch(void* const* d_in, const int* in_sizes, int n_in,
                              void* d_out, int out_size) {
    const float* x1  = (const float*)d_in[0];
    const int*   ei1 = (const int*)  d_in[1];
    const float* ew1 = (const float*)d_in[2];
    const float* x2  = (const float*)d_in[3];
    const int*   ei2 = (const int*)  d_in[4];
    const float* ew2 = (const float*)d_in[5];
    const float* W1  = (const float*)d_in[6];
    const float* b1  = (const float*)d_in[7];
    const float* W2  = (const float*)d_in[8];
    const float* b2  = (const float*)d_in[9];
    float* out = (float*)d_out;

    const int TB = 256;
    k_prep_gemm1<<<dim3(PREP_BLOCKS + G1_BLOCKS, 2), TB>>>(ei1, ew1, ei2, ew2, x1, x2, W1);
    k_scan      <<<dim3(NBLK, 2), SCAN_B>>>();
    k_fill      <<<dim3((EE + TB - 1) / TB, 2), TB>>>(ei1, ew1, ei2, ew2);

    k_aggr1<<<dim3(AGG_BLOCKS, 2), TB>>>(b1);
    dim3 gblk(16, 16);
    k_gemm2<<<dim3(G1_BLOCKS, 2, 2), gblk>>>(W2);
    k_aggr2<<<dim3(AGG_BLOCKS + RST_BLOCKS, 2), TB>>>(b2, out);
}

// round 9
// speedup vs baseline: 1.0075x; 1.0075x over previous
#include <cuda_runtime.h>
#include <cuda_fp16.h>
#include <math.h>

#define NN   50000
#define EE   800000
#define IN_DIM 128
#define O1   64
#define O2   128

#define SCAN_B 1024
#define NBLK   ((NN + SCAN_B - 1) / SCAN_B)   // 49

#define PREP_BLOCKS ((EE + 255) / 256)        // 3125
#define G1_BLOCKS   ((NN + 63) / 64)          // 782
#define AGG_BLOCKS  ((NN * 32 + 255) / 256)   // 6250
#define RST_BLOCKS  98                        // zero g_dc (2 ULL/thread) + g_lk

#define DEG_SCALE 1048576.0f                  // 2^20 fixed point for edge-weight sums

// Scratch (device globals — no allocation allowed). Index 0/1 = tower.
__device__ unsigned long long g_dc[2][NN];    // hi32 = count, lo32 = fixedpoint sum(relu(w))
__device__ unsigned long long g_lk[2][64];    // lookback: hi32 flag (0/1/2), lo32 value
__device__ float  g_dinv[2][NN];
__device__ int    g_off [2][NN + 1];          // exclusive offsets (immutable after scan)
__device__ int    g_rank[2][EE];              // per-edge rank within its dst bucket
__device__ int2   g_edge[2][EE];              // (src, float-bits of norm)
__device__ __half g_h1h[2][NN * O1];          // layer-1 hidden fp16 (gather-bound)
__device__ float  g_z1 [2][NN * O1];
__device__ __half g_h2h[2][NN * O2];          // layer-2 hidden fp16 (gather-bound)

// ---------------------------------------------------------------------------
// packed fp32x2 FMA (sm_103a FFMA2)
// ---------------------------------------------------------------------------
__device__ __forceinline__ void ffma2(float2& acc, float2 a, float2 w) {
    unsigned long long ac, av, wv;
    ac = *(unsigned long long*)&acc;
    av = *(unsigned long long*)&a;
    wv = *(unsigned long long*)&w;
    asm("fma.rn.f32x2 %0, %1, %2, %0;" : "+l"(ac) : "l"(av), "l"(wv));
    acc = *(float2*)&ac;
}

// ---------------------------------------------------------------------------
// Register-tiled GEMM body: C[64-row tile, 64-col tile] = A[N,K] @ W[K,OC]
// 256 flat threads; each thread 4 rows x 4 cols; k paired for fma.rn.f32x2
// Output fp16
// ---------------------------------------------------------------------------
template<int K, int OC>
__device__ __forceinline__ void gemm_body(const float* __restrict__ A,
                                          const float* __restrict__ W,
                                          __half* __restrict__ C,
                                          int rowBlk, int colBase, int tid) {
    __shared__ float2 Wp[(K / 2) * 64];
    int tx = tid & 15;
    int ty = tid >> 4;
    for (int idx = tid; idx < (K / 2) * 64; idx += 256) {
        int kp = idx >> 6, c = idx & 63;
        Wp[idx] = make_float2(W[(2 * kp)     * OC + colBase + c],
                              W[(2 * kp + 1) * OC + colBase + c]);
    }
    __syncthreads();

    int r0 = rowBlk * 64 + ty * 4;
    int c0 = tx * 4;
    float2 acc[4][4];
#pragma unroll
    for (int i = 0; i < 4; i++)
#pragma unroll
        for (int j = 0; j < 4; j++) acc[i][j] = make_float2(0.0f, 0.0f);

#pragma unroll 4
    for (int kk = 0; kk < K; kk += 4) {
        float4 a[4];
#pragma unroll
        for (int i = 0; i < 4; i++) {
            int r = r0 + i;
            a[i] = (r < NN) ? *(const float4*)(A + (size_t)r * K + kk)
                            : make_float4(0.0f, 0.0f, 0.0f, 0.0f);
        }
#pragma unroll
        for (int kp = 0; kp < 2; kp++) {
            const float2* wrow = Wp + ((kk >> 1) + kp) * 64 + c0;
            float4 wA = *(const float4*)(wrow);
            float4 wB = *(const float4*)(wrow + 2);
            float2 w0 = make_float2(wA.x, wA.y);
            float2 w1 = make_float2(wA.z, wA.w);
            float2 w2 = make_float2(wB.x, wB.y);
            float2 w3 = make_float2(wB.z, wB.w);
#pragma unroll
            for (int i = 0; i < 4; i++) {
                float2 ap = kp ? make_float2(a[i].z, a[i].w)
                               : make_float2(a[i].x, a[i].y);
                ffma2(acc[i][0], ap, w0);
                ffma2(acc[i][1], ap, w1);
                ffma2(acc[i][2], ap, w2);
                ffma2(acc[i][3], ap, w3);
            }
        }
    }
#pragma unroll
    for (int i = 0; i < 4; i++) {
        int r = r0 + i;
        if (r < NN) {
            __half2 p0 = __floats2half2_rn(acc[i][0].x + acc[i][0].y,
                                           acc[i][1].x + acc[i][1].y);
            __half2 p1 = __floats2half2_rn(acc[i][2].x + acc[i][2].y,
                                           acc[i][3].x + acc[i][3].y);
            uint2 pk;
            pk.x = *(unsigned*)&p0;
            pk.y = *(unsigned*)&p1;
            *(uint2*)(C + (size_t)r * OC + colBase + c0) = pk;
        }
    }
}

// ---------------------------------------------------------------------------
// fused: packed deg/count atomics + rank capture | GEMM1
// (g_dc and g_lk are zero at entry: BSS-zero on first run, reset by the
//  previous invocation's k_aggr2 tail blocks on every subsequent run)
// ---------------------------------------------------------------------------
__global__ void k_prep_gemm1(const int* __restrict__ ei1, const float* __restrict__ ew1,
                             const int* __restrict__ ei2, const float* __restrict__ ew2,
                             const float* __restrict__ x1, const float* __restrict__ x2,
                             const float* __restrict__ W1) {
    int tw = blockIdx.y;
    if (blockIdx.x < PREP_BLOCKS) {
        const int*   ei = tw ? ei2 : ei1;
        const float* ew = tw ? ew2 : ew1;
        int e = blockIdx.x * 256 + threadIdx.x;
        if (e < EE) {
            int d = ei[EE + e];
            float w = fmaxf(ew[e], 0.0f);          // relu(edge_weight)
            unsigned long long pk =
                (1ULL << 32) | (unsigned long long)__float2uint_rn(w * DEG_SCALE);
            unsigned long long old = atomicAdd(&g_dc[tw][d], pk);
            g_rank[tw][e] = (int)(old >> 32);      // rank within dst bucket
        }
    } else {
        gemm_body<IN_DIM, O1>(tw ? x2 : x1, W1, g_h1h[tw],
                              blockIdx.x - PREP_BLOCKS, 0, threadIdx.x);
    }
}

// ---------------------------------------------------------------------------
// single-pass scan (decoupled lookback) + dinv. grid (NBLK,2) x 1024 threads
// ---------------------------------------------------------------------------
__global__ void k_scan() {
    int tw   = blockIdx.y;
    int b    = blockIdx.x;
    int i    = b * SCAN_B + threadIdx.x;
    int lane = threadIdx.x & 31;
    int wid  = threadIdx.x >> 5;
    unsigned long long dc = (i < NN) ? g_dc[tw][i] : 0ULL;
    int c = (int)(dc >> 32);
    int v = c;
#pragma unroll
    for (int d = 1; d < 32; d <<= 1) {
        int t = __shfl_up_sync(0xffffffffu, v, d);
        if (lane >= d) v += t;
    }
    __shared__ int wsum[32];
    if (lane == 31) wsum[wid] = v;
    __syncthreads();
    if (wid == 0) {
        int w = wsum[lane];
#pragma unroll
        for (int d = 1; d < 32; d <<= 1) {
            int t = __shfl_up_sync(0xffffffffu, w, d);
            if (lane >= d) w += t;
        }
        wsum[lane] = w;
    }
    __syncthreads();
    int add = (wid > 0) ? wsum[wid - 1] : 0;
    int incl = v + add;                   // inclusive within block
    int total = wsum[31];

    __shared__ int s_exc;
    if (threadIdx.x == 0) {
        unsigned long long flag = (b == 0) ? 2ULL : 1ULL;
        atomicExch(&g_lk[tw][b], (flag << 32) | (unsigned)total);
        int exc = 0;
        if (b > 0) {
            int p = b - 1;
            while (true) {
                unsigned long long pv = *((volatile unsigned long long*)&g_lk[tw][p]);
                unsigned f = (unsigned)(pv >> 32);
                if (f == 2u) { exc += (int)(unsigned)pv; break; }
                if (f == 1u) { exc += (int)(unsigned)pv; p--; }
            }
            atomicExch(&g_lk[tw][b], (2ULL << 32) | (unsigned)(total + exc));
        }
        s_exc = exc;
    }
    __syncthreads();
    if (i < NN) {
        g_off[tw][i] = s_exc + incl - c;   // exclusive global offset
        float deg = 2.0f + (float)(unsigned)dc * (1.0f / DEG_SCALE);
        g_dinv[tw][i] = rsqrtf(deg);
    }
    if (b == gridDim.x - 1 && threadIdx.x == 0) g_off[tw][NN] = EE;
}

// ---------------------------------------------------------------------------
// fill: atomic-free — pos = off[d] + rank[e]
// ---------------------------------------------------------------------------
__global__ void k_fill(const int* __restrict__ ei1, const float* __restrict__ ew1,
                       const int* __restrict__ ei2, const float* __restrict__ ew2) {
    int tw = blockIdx.y;
    const int*   ei = tw ? ei2 : ei1;
    const float* ew = tw ? ew2 : ew1;
    int e = blockIdx.x * blockDim.x + threadIdx.x;
    if (e < EE) {
        int s = ei[e], d = ei[EE + e];
        float w = fmaxf(ew[e], 0.0f);
        float nrm = g_dinv[tw][s] * w * g_dinv[tw][d];
        int pos = g_off[tw][d] + g_rank[tw][e];
        g_edge[tw][pos] = make_int2(s, __float_as_int(nrm));
    }
}

__global__ void k_gemm2(const float* __restrict__ W2) {
    int tw = blockIdx.z;
    gemm_body<O1, O2>(g_z1[tw], W2, g_h2h[tw],
                      blockIdx.x, blockIdx.y * 64, threadIdx.y * 16 + threadIdx.x);
}

// ---------------------------------------------------------------------------
// Aggregation 1: warp per node, fp16 SIMD gather-max (HMUL2+HMAX2), 8x unrolled
// ---------------------------------------------------------------------------
__global__ void k_aggr1(const float* __restrict__ b1) {
    int tw   = blockIdx.y;
    int warp = (blockIdx.x * blockDim.x + threadIdx.x) >> 5;
    int lane = threadIdx.x & 31;
    if (warp >= NN) return;
    const int2*   eg = g_edge[tw];
    const __half* h  = g_h1h[tw];
    int beg = g_off[tw][warp];
    int end = g_off[tw][warp + 1];
    float dv = g_dinv[tw][warp];
    __half2 slh = __float2half2_rn(2.0f * dv * dv);
    unsigned selfpk = *(const unsigned*)(h + (size_t)warp * O1 + lane * 2);
    __half2 m = __hmul2(*(__half2*)&selfpk, slh);
    int j = beg;
    for (; j + 8 <= end; j += 8) {
        int2 e[8];
        unsigned v[8];
#pragma unroll
        for (int q = 0; q < 8; q++) e[q] = eg[j + q];
#pragma unroll
        for (int q = 0; q < 8; q++)
            v[q] = *(const unsigned*)(h + (size_t)e[q].x * O1 + lane * 2);
#pragma unroll
        for (int q = 0; q < 8; q++) {
            __half2 wh = __float2half2_rn(__int_as_float(e[q].y));
            m = __hmax2(m, __hmul2(*(__half2*)&v[q], wh));
        }
    }
    for (; j < end; j++) {
        int2 e = eg[j];
        unsigned v = *(const unsigned*)(h + (size_t)e.x * O1 + lane * 2);
        __half2 wh = __float2half2_rn(__int_as_float(e.y));
        m = __hmax2(m, __hmul2(*(__half2*)&v, wh));
    }
    float2 f = __half22float2(m);
    float m0 = f.x, m1 = f.y;
    if (!isfinite(m0)) m0 = 0.0f;
    if (!isfinite(m1)) m1 = 0.0f;
    float2 bv = *(const float2*)(b1 + lane * 2);
    *(float2*)(g_z1[tw] + (size_t)warp * O1 + lane * 2) = make_float2(m0 + bv.x, m1 + bv.y);
}

// ---------------------------------------------------------------------------
// Aggregation 2: warp per node over 128 fp16 feats (8B/lane), fp16 SIMD max,
// 8x unrolled; tail blocks reset g_dc / g_lk for the next invocation
// ---------------------------------------------------------------------------
__global__ void k_aggr2(const float* __restrict__ b2, float* __restrict__ out) {
    int tw   = blockIdx.y;
    if (blockIdx.x >= AGG_BLOCKS) {
        // reset scratch for next invocation
        int rb  = blockIdx.x - AGG_BLOCKS;
        int idx = (rb * 256 + threadIdx.x) * 2;
        if (idx     < NN) g_dc[tw][idx]     = 0ULL;
        if (idx + 1 < NN) g_dc[tw][idx + 1] = 0ULL;
        if (rb == 0 && threadIdx.x < 64) g_lk[tw][threadIdx.x] = 0ULL;
        return;
    }
    int warp = (blockIdx.x * blockDim.x + threadIdx.x) >> 5;
    int lane = threadIdx.x & 31;
    if (warp >= NN) return;
    const int2*   eg = g_edge[tw];
    const __half* h  = g_h2h[tw];
    float* op = out + (size_t)tw * NN * O2;
    int beg = g_off[tw][warp];
    int end = g_off[tw][warp + 1];
    float dv = g_dinv[tw][warp];
    __half2 slh = __float2half2_rn(2.0f * dv * dv);
    uint2 selfpk = *(const uint2*)(h + (size_t)warp * O2 + lane * 4);
    __half2 mA = __hmul2(*(__half2*)&selfpk.x, slh);
    __half2 mB = __hmul2(*(__half2*)&selfpk.y, slh);
    int j = beg;
    for (; j + 8 <= end; j += 8) {
        int2 e[8];
        uint2 v[8];
#pragma unroll
        for (int q = 0; q < 8; q++) e[q] = eg[j + q];
#pragma unroll
        for (int q = 0; q < 8; q++)
            v[q] = *(const uint2*)(h + (size_t)e[q].x * O2 + lane * 4);
#pragma unroll
        for (int q = 0; q < 8; q++) {
            __half2 wh = __float2half2_rn(__int_as_float(e[q].y));
            mA = __hmax2(mA, __hmul2(*(__half2*)&v[q].x, wh));
            mB = __hmax2(mB, __hmul2(*(__half2*)&v[q].y, wh));
        }
    }
    for (; j < end; j++) {
        int2 e = eg[j];
        uint2 v = *(const uint2*)(h + (size_t)e.x * O2 + lane * 4);
        __half2 wh = __float2half2_rn(__int_as_float(e.y));
        mA = __hmax2(mA, __hmul2(*(__half2*)&v.x, wh));
        mB = __hmax2(mB, __hmul2(*(__half2*)&v.y, wh));
    }
    float2 fA = __half22float2(mA);
    float2 fB = __half22float2(mB);
    float m0 = fA.x, m1 = fA.y, m2 = fB.x, m3 = fB.y;
    if (!isfinite(m0)) m0 = 0.0f;
    if (!isfinite(m1)) m1 = 0.0f;
    if (!isfinite(m2)) m2 = 0.0f;
    if (!isfinite(m3)) m3 = 0.0f;
    float4 bv = *(const float4*)(b2 + lane * 4);
    *(float4*)(op + (size_t)warp * O2 + lane * 4) =
        make_float4(m0 + bv.x, m1 + bv.y, m2 + bv.z, m3 + bv.w);
}

// ---------------------------------------------------------------------------
// launch
// ---------------------------------------------------------------------------
extern "C" void kernel_launch(void* const* d_in, const int* in_sizes, int n_in,
                              void* d_out, int out_size) {
    const float* x1  = (const float*)d_in[0];
    const int*   ei1 = (const int*)  d_in[1];
    const float* ew1 = (const float*)d_in[2];
    const float* x2  = (const float*)d_in[3];
    const int*   ei2 = (const int*)  d_in[4];
    const float* ew2 = (const float*)d_in[5];
    const float* W1  = (const float*)d_in[6];
    const float* b1  = (const float*)d_in[7];
    const float* W2  = (const float*)d_in[8];
    const float* b2  = (const float*)d_in[9];
    float* out = (float*)d_out;

    const int TB = 256;
    k_prep_gemm1<<<dim3(PREP_BLOCKS + G1_BLOCKS, 2), TB>>>(ei1, ew1, ei2, ew2, x1, x2, W1);
    k_scan      <<<dim3(NBLK, 2), SCAN_B>>>();
    k_fill      <<<dim3((EE + TB - 1) / TB, 2), TB>>>(ei1, ew1, ei2, ew2);

    k_aggr1<<<dim3(AGG_BLOCKS, 2), TB>>>(b1);
    dim3 gblk(16, 16);
    k_gemm2<<<dim3(G1_BLOCKS, 2, 2), gblk>>>(W2);
    k_aggr2<<<dim3(AGG_BLOCKS + RST_BLOCKS, 2), TB>>>(b2, out);
}

// round 10
// speedup vs baseline: 1.0600x; 1.0520x over previous
#include <cuda_runtime.h>
#include <cuda_fp16.h>
#include <math.h>

#define NN   50000
#define EE   800000
#define IN_DIM 128
#define O1   64
#define O2   128

#define SCAN_B 1024
#define NBLK   ((NN + SCAN_B - 1) / SCAN_B)   // 49

#define PREP_BLOCKS ((EE + 255) / 256)        // 3125
#define G1_BLOCKS   ((NN + 63) / 64)          // 782
#define AGG_BLOCKS  ((NN / 2 * 32 + 255) / 256) // 3125 (2 nodes per warp)
#define RST_BLOCKS  98                        // zero g_dc (2 ULL/thread) + g_lk

#define DEG_SCALE 1048576.0f                  // 2^20 fixed point for edge-weight sums

// Scratch (device globals — no allocation allowed). Index 0/1 = tower.
__device__ unsigned long long g_dc[2][NN];    // hi32 = count, lo32 = fixedpoint sum(relu(w))
__device__ unsigned long long g_lk[2][64];    // lookback: hi32 flag (0/1/2), lo32 value
__device__ float  g_dinv[2][NN];
__device__ int    g_off [2][NN + 1];          // exclusive offsets (immutable after scan)
__device__ int    g_rank[2][EE];              // per-edge rank within its dst bucket
__device__ int2   g_edge[2][EE];              // (src, half2(norm,norm) bits)
__device__ __half g_h1h[2][NN * O1];          // layer-1 hidden fp16 (gather-bound)
__device__ float  g_z1 [2][NN * O1];
__device__ __half g_h2h[2][NN * O2];          // layer-2 hidden fp16 (gather-bound)

// ---------------------------------------------------------------------------
// packed fp32x2 FMA (sm_103a FFMA2)
// ---------------------------------------------------------------------------
__device__ __forceinline__ void ffma2(float2& acc, float2 a, float2 w) {
    unsigned long long ac, av, wv;
    ac = *(unsigned long long*)&acc;
    av = *(unsigned long long*)&a;
    wv = *(unsigned long long*)&w;
    asm("fma.rn.f32x2 %0, %1, %2, %0;" : "+l"(ac) : "l"(av), "l"(wv));
    acc = *(float2*)&ac;
}

// ---------------------------------------------------------------------------
// Register-tiled GEMM body: C[64-row tile, 64-col tile] = A[N,K] @ W[K,OC]
// 256 flat threads; each thread 4 rows x 4 cols; k paired for fma.rn.f32x2
// Output fp16
// ---------------------------------------------------------------------------
template<int K, int OC>
__device__ __forceinline__ void gemm_body(const float* __restrict__ A,
                                          const float* __restrict__ W,
                                          __half* __restrict__ C,
                                          int rowBlk, int colBase, int tid) {
    __shared__ float2 Wp[(K / 2) * 64];
    int tx = tid & 15;
    int ty = tid >> 4;
    for (int idx = tid; idx < (K / 2) * 64; idx += 256) {
        int kp = idx >> 6, c = idx & 63;
        Wp[idx] = make_float2(W[(2 * kp)     * OC + colBase + c],
                              W[(2 * kp + 1) * OC + colBase + c]);
    }
    __syncthreads();

    int r0 = rowBlk * 64 + ty * 4;
    int c0 = tx * 4;
    float2 acc[4][4];
#pragma unroll
    for (int i = 0; i < 4; i++)
#pragma unroll
        for (int j = 0; j < 4; j++) acc[i][j] = make_float2(0.0f, 0.0f);

#pragma unroll 4
    for (int kk = 0; kk < K; kk += 4) {
        float4 a[4];
#pragma unroll
        for (int i = 0; i < 4; i++) {
            int r = r0 + i;
            a[i] = (r < NN) ? *(const float4*)(A + (size_t)r * K + kk)
                            : make_float4(0.0f, 0.0f, 0.0f, 0.0f);
        }
#pragma unroll
        for (int kp = 0; kp < 2; kp++) {
            const float2* wrow = Wp + ((kk >> 1) + kp) * 64 + c0;
            float4 wA = *(const float4*)(wrow);
            float4 wB = *(const float4*)(wrow + 2);
            float2 w0 = make_float2(wA.x, wA.y);
            float2 w1 = make_float2(wA.z, wA.w);
            float2 w2 = make_float2(wB.x, wB.y);
            float2 w3 = make_float2(wB.z, wB.w);
#pragma unroll
            for (int i = 0; i < 4; i++) {
                float2 ap = kp ? make_float2(a[i].z, a[i].w)
                               : make_float2(a[i].x, a[i].y);
                ffma2(acc[i][0], ap, w0);
                ffma2(acc[i][1], ap, w1);
                ffma2(acc[i][2], ap, w2);
                ffma2(acc[i][3], ap, w3);
            }
        }
    }
#pragma unroll
    for (int i = 0; i < 4; i++) {
        int r = r0 + i;
        if (r < NN) {
            __half2 p0 = __floats2half2_rn(acc[i][0].x + acc[i][0].y,
                                           acc[i][1].x + acc[i][1].y);
            __half2 p1 = __floats2half2_rn(acc[i][2].x + acc[i][2].y,
                                           acc[i][3].x + acc[i][3].y);
            uint2 pk;
            pk.x = *(unsigned*)&p0;
            pk.y = *(unsigned*)&p1;
            *(uint2*)(C + (size_t)r * OC + colBase + c0) = pk;
        }
    }
}

// ---------------------------------------------------------------------------
// fused: packed deg/count atomics + rank capture | GEMM1
// (g_dc and g_lk are zero at entry: BSS-zero on first run, reset by the
//  previous invocation's k_aggr2 tail blocks on every subsequent run)
// ---------------------------------------------------------------------------
__global__ void k_prep_gemm1(const int* __restrict__ ei1, const float* __restrict__ ew1,
                             const int* __restrict__ ei2, const float* __restrict__ ew2,
                             const float* __restrict__ x1, const float* __restrict__ x2,
                             const float* __restrict__ W1) {
    int tw = blockIdx.y;
    if (blockIdx.x < PREP_BLOCKS) {
        const int*   ei = tw ? ei2 : ei1;
        const float* ew = tw ? ew2 : ew1;
        int e = blockIdx.x * 256 + threadIdx.x;
        if (e < EE) {
            int d = ei[EE + e];
            float w = fmaxf(ew[e], 0.0f);          // relu(edge_weight)
            unsigned long long pk =
                (1ULL << 32) | (unsigned long long)__float2uint_rn(w * DEG_SCALE);
            unsigned long long old = atomicAdd(&g_dc[tw][d], pk);
            g_rank[tw][e] = (int)(old >> 32);      // rank within dst bucket
        }
    } else {
        gemm_body<IN_DIM, O1>(tw ? x2 : x1, W1, g_h1h[tw],
                              blockIdx.x - PREP_BLOCKS, 0, threadIdx.x);
    }
}

// ---------------------------------------------------------------------------
// single-pass scan (decoupled lookback) + dinv. grid (NBLK,2) x 1024 threads
// ---------------------------------------------------------------------------
__global__ void k_scan() {
    int tw   = blockIdx.y;
    int b    = blockIdx.x;
    int i    = b * SCAN_B + threadIdx.x;
    int lane = threadIdx.x & 31;
    int wid  = threadIdx.x >> 5;
    unsigned long long dc = (i < NN) ? g_dc[tw][i] : 0ULL;
    int c = (int)(dc >> 32);
    int v = c;
#pragma unroll
    for (int d = 1; d < 32; d <<= 1) {
        int t = __shfl_up_sync(0xffffffffu, v, d);
        if (lane >= d) v += t;
    }
    __shared__ int wsum[32];
    if (lane == 31) wsum[wid] = v;
    __syncthreads();
    if (wid == 0) {
        int w = wsum[lane];
#pragma unroll
        for (int d = 1; d < 32; d <<= 1) {
            int t = __shfl_up_sync(0xffffffffu, w, d);
            if (lane >= d) w += t;
        }
        wsum[lane] = w;
    }
    __syncthreads();
    int add = (wid > 0) ? wsum[wid - 1] : 0;
    int incl = v + add;                   // inclusive within block
    int total = wsum[31];

    __shared__ int s_exc;
    if (threadIdx.x == 0) {
        unsigned long long flag = (b == 0) ? 2ULL : 1ULL;
        atomicExch(&g_lk[tw][b], (flag << 32) | (unsigned)total);
        int exc = 0;
        if (b > 0) {
            int p = b - 1;
            while (true) {
                unsigned long long pv = *((volatile unsigned long long*)&g_lk[tw][p]);
                unsigned f = (unsigned)(pv >> 32);
                if (f == 2u) { exc += (int)(unsigned)pv; break; }
                if (f == 1u) { exc += (int)(unsigned)pv; p--; }
            }
            atomicExch(&g_lk[tw][b], (2ULL << 32) | (unsigned)(total + exc));
        }
        s_exc = exc;
    }
    __syncthreads();
    if (i < NN) {
        g_off[tw][i] = s_exc + incl - c;   // exclusive global offset
        float deg = 2.0f + (float)(unsigned)dc * (1.0f / DEG_SCALE);
        g_dinv[tw][i] = rsqrtf(deg);
    }
    if (b == gridDim.x - 1 && threadIdx.x == 0) g_off[tw][NN] = EE;
}

// ---------------------------------------------------------------------------
// fill: atomic-free — pos = off[d] + rank[e]; norm pre-packed as half2
// ---------------------------------------------------------------------------
__global__ void k_fill(const int* __restrict__ ei1, const float* __restrict__ ew1,
                       const int* __restrict__ ei2, const float* __restrict__ ew2) {
    int tw = blockIdx.y;
    const int*   ei = tw ? ei2 : ei1;
    const float* ew = tw ? ew2 : ew1;
    int e = blockIdx.x * blockDim.x + threadIdx.x;
    if (e < EE) {
        int s = ei[e], d = ei[EE + e];
        float w = fmaxf(ew[e], 0.0f);
        float nrm = g_dinv[tw][s] * w * g_dinv[tw][d];
        __half2 nh = __float2half2_rn(nrm);
        int pos = g_off[tw][d] + g_rank[tw][e];
        g_edge[tw][pos] = make_int2(s, *(int*)&nh);
    }
}

__global__ void k_gemm2(const float* __restrict__ W2) {
    int tw = blockIdx.z;
    gemm_body<O1, O2>(g_z1[tw], W2, g_h2h[tw],
                      blockIdx.x, blockIdx.y * 64, threadIdx.y * 16 + threadIdx.x);
}

// ---------------------------------------------------------------------------
// Aggregation 1: 2 nodes per warp (16 lanes each, uint2 = 4 fp16 per lane)
// ---------------------------------------------------------------------------
__global__ void k_aggr1(const float* __restrict__ b1) {
    int tw    = blockIdx.y;
    int gwarp = (blockIdx.x * blockDim.x + threadIdx.x) >> 5;
    int lane  = threadIdx.x & 31;
    int node  = gwarp * 2 + (lane >> 4);
    int ln    = lane & 15;
    if (node >= NN) return;
    const int2*   eg = g_edge[tw];
    const __half* h  = g_h1h[tw];
    int beg = g_off[tw][node];
    int end = g_off[tw][node + 1];
    float dv = g_dinv[tw][node];
    __half2 slh = __float2half2_rn(2.0f * dv * dv);
    uint2 selfpk = *(const uint2*)(h + (size_t)node * O1 + ln * 4);
    __half2 mA = __hmul2(*(__half2*)&selfpk.x, slh);
    __half2 mB = __hmul2(*(__half2*)&selfpk.y, slh);
    int j = beg;
    for (; j + 4 <= end; j += 4) {
        int2 e0 = eg[j], e1 = eg[j + 1], e2 = eg[j + 2], e3 = eg[j + 3];
        uint2 v0 = *(const uint2*)(h + (size_t)e0.x * O1 + ln * 4);
        uint2 v1 = *(const uint2*)(h + (size_t)e1.x * O1 + ln * 4);
        uint2 v2 = *(const uint2*)(h + (size_t)e2.x * O1 + ln * 4);
        uint2 v3 = *(const uint2*)(h + (size_t)e3.x * O1 + ln * 4);
        mA = __hmax2(mA, __hmul2(*(__half2*)&v0.x, *(__half2*)&e0.y));
        mB = __hmax2(mB, __hmul2(*(__half2*)&v0.y, *(__half2*)&e0.y));
        mA = __hmax2(mA, __hmul2(*(__half2*)&v1.x, *(__half2*)&e1.y));
        mB = __hmax2(mB, __hmul2(*(__half2*)&v1.y, *(__half2*)&e1.y));
        mA = __hmax2(mA, __hmul2(*(__half2*)&v2.x, *(__half2*)&e2.y));
        mB = __hmax2(mB, __hmul2(*(__half2*)&v2.y, *(__half2*)&e2.y));
        mA = __hmax2(mA, __hmul2(*(__half2*)&v3.x, *(__half2*)&e3.y));
        mB = __hmax2(mB, __hmul2(*(__half2*)&v3.y, *(__half2*)&e3.y));
    }
    for (; j < end; j++) {
        int2 e = eg[j];
        uint2 v = *(const uint2*)(h + (size_t)e.x * O1 + ln * 4);
        mA = __hmax2(mA, __hmul2(*(__half2*)&v.x, *(__half2*)&e.y));
        mB = __hmax2(mB, __hmul2(*(__half2*)&v.y, *(__half2*)&e.y));
    }
    float2 fA = __half22float2(mA);
    float2 fB = __half22float2(mB);
    float m0 = fA.x, m1 = fA.y, m2 = fB.x, m3 = fB.y;
    if (!isfinite(m0)) m0 = 0.0f;
    if (!isfinite(m1)) m1 = 0.0f;
    if (!isfinite(m2)) m2 = 0.0f;
    if (!isfinite(m3)) m3 = 0.0f;
    float4 bv = *(const float4*)(b1 + ln * 4);
    *(float4*)(g_z1[tw] + (size_t)node * O1 + ln * 4) =
        make_float4(m0 + bv.x, m1 + bv.y, m2 + bv.z, m3 + bv.w);
}

// ---------------------------------------------------------------------------
// Aggregation 2: 2 nodes per warp (16 lanes each, uint4 = 8 fp16 per lane);
// tail blocks reset g_dc / g_lk for the next invocation
// ---------------------------------------------------------------------------
__device__ __forceinline__ void max8_half(__half2& mA, __half2& mB, __half2& mC, __half2& mD,
                                          uint4 pk, __half2 wh) {
    mA = __hmax2(mA, __hmul2(*(__half2*)&pk.x, wh));
    mB = __hmax2(mB, __hmul2(*(__half2*)&pk.y, wh));
    mC = __hmax2(mC, __hmul2(*(__half2*)&pk.z, wh));
    mD = __hmax2(mD, __hmul2(*(__half2*)&pk.w, wh));
}

__global__ void k_aggr2(const float* __restrict__ b2, float* __restrict__ out) {
    int tw = blockIdx.y;
    if (blockIdx.x >= AGG_BLOCKS) {
        // reset scratch for next invocation
        int rb  = blockIdx.x - AGG_BLOCKS;
        int idx = (rb * 256 + threadIdx.x) * 2;
        if (idx     < NN) g_dc[tw][idx]     = 0ULL;
        if (idx + 1 < NN) g_dc[tw][idx + 1] = 0ULL;
        if (rb == 0 && threadIdx.x < 64) g_lk[tw][threadIdx.x] = 0ULL;
        return;
    }
    int gwarp = (blockIdx.x * blockDim.x + threadIdx.x) >> 5;
    int lane  = threadIdx.x & 31;
    int node  = gwarp * 2 + (lane >> 4);
    int ln    = lane & 15;
    if (node >= NN) return;
    const int2*   eg = g_edge[tw];
    const __half* h  = g_h2h[tw];
    float* op = out + (size_t)tw * NN * O2;
    int beg = g_off[tw][node];
    int end = g_off[tw][node + 1];
    float dv = g_dinv[tw][node];
    __half2 slh = __float2half2_rn(2.0f * dv * dv);
    uint4 selfpk = *(const uint4*)(h + (size_t)node * O2 + ln * 8);
    __half2 mA = __hmul2(*(__half2*)&selfpk.x, slh);
    __half2 mB = __hmul2(*(__half2*)&selfpk.y, slh);
    __half2 mC = __hmul2(*(__half2*)&selfpk.z, slh);
    __half2 mD = __hmul2(*(__half2*)&selfpk.w, slh);
    int j = beg;
    for (; j + 4 <= end; j += 4) {
        int2 e0 = eg[j], e1 = eg[j + 1], e2 = eg[j + 2], e3 = eg[j + 3];
        uint4 v0 = *(const uint4*)(h + (size_t)e0.x * O2 + ln * 8);
        uint4 v1 = *(const uint4*)(h + (size_t)e1.x * O2 + ln * 8);
        uint4 v2 = *(const uint4*)(h + (size_t)e2.x * O2 + ln * 8);
        uint4 v3 = *(const uint4*)(h + (size_t)e3.x * O2 + ln * 8);
        max8_half(mA, mB, mC, mD, v0, *(__half2*)&e0.y);
        max8_half(mA, mB, mC, mD, v1, *(__half2*)&e1.y);
        max8_half(mA, mB, mC, mD, v2, *(__half2*)&e2.y);
        max8_half(mA, mB, mC, mD, v3, *(__half2*)&e3.y);
    }
    for (; j < end; j++) {
        int2 e = eg[j];
        uint4 v = *(const uint4*)(h + (size_t)e.x * O2 + ln * 8);
        max8_half(mA, mB, mC, mD, v, *(__half2*)&e.y);
    }
    float2 fA = __half22float2(mA);
    float2 fB = __half22float2(mB);
    float2 fC = __half22float2(mC);
    float2 fD = __half22float2(mD);
    float m[8] = {fA.x, fA.y, fB.x, fB.y, fC.x, fC.y, fD.x, fD.y};
#pragma unroll
    for (int q = 0; q < 8; q++)
        if (!isfinite(m[q])) m[q] = 0.0f;
    float4 bv0 = *(const float4*)(b2 + ln * 8);
    float4 bv1 = *(const float4*)(b2 + ln * 8 + 4);
    float* dst = op + (size_t)node * O2 + ln * 8;
    *(float4*)(dst)     = make_float4(m[0] + bv0.x, m[1] + bv0.y, m[2] + bv0.z, m[3] + bv0.w);
    *(float4*)(dst + 4) = make_float4(m[4] + bv1.x, m[5] + bv1.y, m[6] + bv1.z, m[7] + bv1.w);
}

// ---------------------------------------------------------------------------
// launch
// ---------------------------------------------------------------------------
extern "C" void kernel_launch(void* const* d_in, const int* in_sizes, int n_in,
                              void* d_out, int out_size) {
    const float* x1  = (const float*)d_in[0];
    const int*   ei1 = (const int*)  d_in[1];
    const float* ew1 = (const float*)d_in[2];
    const float* x2  = (const float*)d_in[3];
    const int*   ei2 = (const int*)  d_in[4];
    const float* ew2 = (const float*)d_in[5];
    const float* W1  = (const float*)d_in[6];
    const float* b1  = (const float*)d_in[7];
    const float* W2  = (const float*)d_in[8];
    const float* b2  = (const float*)d_in[9];
    float* out = (float*)d_out;

    const int TB = 256;
    k_prep_gemm1<<<dim3(PREP_BLOCKS + G1_BLOCKS, 2), TB>>>(ei1, ew1, ei2, ew2, x1, x2, W1);
    k_scan      <<<dim3(NBLK, 2), SCAN_B>>>();
    k_fill      <<<dim3((EE + TB - 1) / TB, 2), TB>>>(ei1, ew1, ei2, ew2);

    k_aggr1<<<dim3(AGG_BLOCKS, 2), TB>>>(b1);
    dim3 gblk(16, 16);
    k_gemm2<<<dim3(G1_BLOCKS, 2, 2), gblk>>>(W2);
    k_aggr2<<<dim3(AGG_BLOCKS + RST_BLOCKS, 2), TB>>>(b2, out);
}